// round 8
// baseline (speedup 1.0000x reference)
#include <cuda_runtime.h>
#include <cuda_bf16.h>
#include <cuda_fp16.h>
#include <cuda_fp8.h>
#include <cstdint>

#define N_ROWS      12288        // L1_INPUT_SIZE
#define N_COLS      1030         // L1_OUTPUT_SIZE
#define HID         1024
#define STRIDE8     1040         // padded fp8 row stride bytes (16B multiple)
#define BATCH       8192
#define NFEAT       32
#define L2IN        2048
#define W_SCALE     128.0f       // weight scale into e4m3 normal range
#define INV_SCALE   0.0078125f   // 1/128
#define PSQT_K      0.08f        // 0.5 / (400/64)
#define GPR         260          // groups of 4 cols per row (260*4 = 1040)

// fp8(e4m3) copy of W1*128 (module-static, no runtime alloc)
__device__ __align__(128) unsigned char g_W1f8[(size_t)N_ROWS * STRIDE8];

// ---------------------------------------------------------------------------
// W1 fp32 -> fp8 conversion (R2-proven shape: u32 store per thread)
// ---------------------------------------------------------------------------
__global__ void convert_kernel(const float* __restrict__ W1) {
    int gid = blockIdx.x * blockDim.x + threadIdx.x;
    if (gid >= N_ROWS * GPR) return;
    const int r   = gid / GPR;
    const int g   = gid - r * GPR;
    const int col = g * 4;
    const float* src = W1 + (size_t)r * N_COLS + col;

    float4 w;
    if (col + 4 <= N_COLS) {
        const float2 a = *reinterpret_cast<const float2*>(src);
        const float2 b = *reinterpret_cast<const float2*>(src + 2);
        w = make_float4(a.x, a.y, b.x, b.y);
    } else {
        w.x = (col + 0 < N_COLS) ? src[0] : 0.f;
        w.y = (col + 1 < N_COLS) ? src[1] : 0.f;
        w.z = (col + 2 < N_COLS) ? src[2] : 0.f;
        w.w = (col + 3 < N_COLS) ? src[3] : 0.f;
    }
    const __nv_fp8x2_storage_t lo =
        __nv_cvt_float2_to_fp8x2(make_float2(w.x * W_SCALE, w.y * W_SCALE),
                                 __NV_SATFINITE, __NV_E4M3);
    const __nv_fp8x2_storage_t hi =
        __nv_cvt_float2_to_fp8x2(make_float2(w.z * W_SCALE, w.w * W_SCALE),
                                 __NV_SATFINITE, __NV_E4M3);
    const uint32_t packed = (uint32_t)lo | ((uint32_t)hi << 16);
    *reinterpret_cast<uint32_t*>(g_W1f8 + (size_t)r * STRIDE8 + col) = packed;
}

// ---------------------------------------------------------------------------
// unpack u32 (4×e4m3) -> two half2, fused multiply-accumulate with vh
// ---------------------------------------------------------------------------
__device__ __forceinline__ void fma4_fp8(half2& a0, half2& a1, uint32_t w, half2 vh) {
    uint32_t h0, h1;
    asm("{\n\t"
        ".reg .b16 lo, hi;\n\t"
        "mov.b32 {lo, hi}, %2;\n\t"
        "cvt.rn.f16x2.e4m3x2 %0, lo;\n\t"
        "cvt.rn.f16x2.e4m3x2 %1, hi;\n\t"
        "}" : "=r"(h0), "=r"(h1) : "r"(w));
    a0 = __hfma2(*reinterpret_cast<half2*>(&h0), vh, a0);
    a1 = __hfma2(*reinterpret_cast<half2*>(&h1), vh, a1);
}

// ---------------------------------------------------------------------------
// Main fused kernel: one CTA per batch row, 128 threads, 8 cols/thread/side,
// 4-deep register prefetch, packed int2 offsets, L2-only weight loads.
// ---------------------------------------------------------------------------
__global__ __launch_bounds__(128)
void fwd_kernel(const int*   __restrict__ x,
                const int*   __restrict__ y,
                const float* __restrict__ v,
                const int*   __restrict__ s,
                const float* __restrict__ b1,
                const float* __restrict__ W2,
                const float* __restrict__ b2,
                float*       __restrict__ out)
{
    __shared__ int2     sxy[NFEAT + 4];    // {offx, offy} bytes; +4 pad for tail prefetch
    __shared__ uint32_t svh[NFEAT];        // v as half2 bits
    __shared__ int      ss_sh;
    __shared__ float    red[4];

    const int b = blockIdx.x;
    const int t = threadIdx.x;

    if (t < NFEAT) {
        const int gi = b * NFEAT + t;
        sxy[t] = make_int2(x[gi] * STRIDE8, y[gi] * STRIDE8);
        const half2 vh = __float2half2_rn(v[gi]);
        svh[t] = *reinterpret_cast<const uint32_t*>(&vh);
    } else if (t < NFEAT + 4) {            // pad so tail prefetches stay in-bounds
        sxy[t] = make_int2(0, 0);
    } else if (t == 64) {
        ss_sh = s[b];
    }
    __syncthreads();

    const unsigned char* basep = g_W1f8 + t * 8;   // this thread's 8 fp8 columns

    // ---- prime the 4-deep prefetch pipeline (L2-only loads) ----
    uint2 px[4], py[4];
#pragma unroll
    for (int i = 0; i < 4; ++i) {
        const int2 o = sxy[i];
        px[i] = __ldcg(reinterpret_cast<const uint2*>(basep + o.x));
        py[i] = __ldcg(reinterpret_cast<const uint2*>(basep + o.y));
    }

    half2 ax[4], ay[4];
#pragma unroll
    for (int j = 0; j < 4; ++j) { ax[j] = __float2half2_rn(0.f); ay[j] = __float2half2_rn(0.f); }

#pragma unroll 8
    for (int a = 0; a < NFEAT; ++a) {
        const int slot = a & 3;
        const uint2 wx = px[slot];
        const uint2 wy = py[slot];
        const int2  on = sxy[a + 4];       // one LDS.64 for both next offsets
        px[slot] = __ldcg(reinterpret_cast<const uint2*>(basep + on.x));
        py[slot] = __ldcg(reinterpret_cast<const uint2*>(basep + on.y));

        half2 vh; *reinterpret_cast<uint32_t*>(&vh) = svh[a];
        fma4_fp8(ax[0], ax[1], wx.x, vh);
        fma4_fp8(ax[2], ax[3], wx.y, vh);
        fma4_fp8(ay[0], ay[1], wy.x, vh);
        fma4_fp8(ay[2], ay[3], wy.y, vh);
    }

    // ---- epilogue: relu(acc/128 + b1) dot W2[ss] ----
    const int ss = ss_sh;
    const int col0 = t * 8;
    const float4 b1a = *reinterpret_cast<const float4*>(b1 + col0);
    const float4 b1b = *reinterpret_cast<const float4*>(b1 + col0 + 4);
    const float* w2row = W2 + (size_t)ss * L2IN;
    const float4 wxa = *reinterpret_cast<const float4*>(w2row + col0);
    const float4 wxb = *reinterpret_cast<const float4*>(w2row + col0 + 4);
    const float4 wya = *reinterpret_cast<const float4*>(w2row + HID + col0);
    const float4 wyb = *reinterpret_cast<const float4*>(w2row + HID + col0 + 4);

    const float2 fx0 = __half22float2(ax[0]);
    const float2 fx1 = __half22float2(ax[1]);
    const float2 fx2 = __half22float2(ax[2]);
    const float2 fx3 = __half22float2(ax[3]);
    const float2 fy0 = __half22float2(ay[0]);
    const float2 fy1 = __half22float2(ay[1]);
    const float2 fy2 = __half22float2(ay[2]);
    const float2 fy3 = __half22float2(ay[3]);

    float local = 0.f;
    local = fmaf(fmaxf(fmaf(fx0.x, INV_SCALE, b1a.x), 0.f), wxa.x, local);
    local = fmaf(fmaxf(fmaf(fx0.y, INV_SCALE, b1a.y), 0.f), wxa.y, local);
    local = fmaf(fmaxf(fmaf(fx1.x, INV_SCALE, b1a.z), 0.f), wxa.z, local);
    local = fmaf(fmaxf(fmaf(fx1.y, INV_SCALE, b1a.w), 0.f), wxa.w, local);
    local = fmaf(fmaxf(fmaf(fx2.x, INV_SCALE, b1b.x), 0.f), wxb.x, local);
    local = fmaf(fmaxf(fmaf(fx2.y, INV_SCALE, b1b.y), 0.f), wxb.y, local);
    local = fmaf(fmaxf(fmaf(fx3.x, INV_SCALE, b1b.z), 0.f), wxb.z, local);
    local = fmaf(fmaxf(fmaf(fx3.y, INV_SCALE, b1b.w), 0.f), wxb.w, local);

    local = fmaf(fmaxf(fmaf(fy0.x, INV_SCALE, b1a.x), 0.f), wya.x, local);
    local = fmaf(fmaxf(fmaf(fy0.y, INV_SCALE, b1a.y), 0.f), wya.y, local);
    local = fmaf(fmaxf(fmaf(fy1.x, INV_SCALE, b1a.z), 0.f), wya.z, local);
    local = fmaf(fmaxf(fmaf(fy1.y, INV_SCALE, b1a.w), 0.f), wya.w, local);
    local = fmaf(fmaxf(fmaf(fy2.x, INV_SCALE, b1b.x), 0.f), wyb.x, local);
    local = fmaf(fmaxf(fmaf(fy2.y, INV_SCALE, b1b.y), 0.f), wyb.y, local);
    local = fmaf(fmaxf(fmaf(fy3.x, INV_SCALE, b1b.z), 0.f), wyb.z, local);
    local = fmaf(fmaxf(fmaf(fy3.y, INV_SCALE, b1b.w), 0.f), wyb.w, local);

    // ---- psqt term: (x2 - y2) * PSQT_K ; b1 cancels in the difference ----
    if (t < 64) {
        const int a  = t & 31;
        const int sp = t >> 5;               // 0 = x, 1 = y
        const int2 o = sxy[a];
        const int off = sp ? o.y : o.x;
        const unsigned char wb = g_W1f8[(size_t)off + HID + ss];
        const float wgt = __half2float(
            __nv_cvt_fp8_to_halfraw((__nv_fp8_storage_t)wb, __NV_E4M3));
        half2 vh; *reinterpret_cast<uint32_t*>(&vh) = svh[a];
        const float p = __half2float(__low2half(vh)) * wgt * (PSQT_K * INV_SCALE);
        local += sp ? -p : p;
    }

    // ---- block reduction ----
#pragma unroll
    for (int o = 16; o > 0; o >>= 1)
        local += __shfl_down_sync(0xffffffffu, local, o);
    if ((t & 31) == 0) red[t >> 5] = local;
    __syncthreads();
    if (t == 0) {
        const float c = red[0] + red[1] + red[2] + red[3] + b2[ss];
        out[b] = 1.0f / (1.0f + expf(-c));
    }
}

// ---------------------------------------------------------------------------
extern "C" void kernel_launch(void* const* d_in, const int* in_sizes, int n_in,
                              void* d_out, int out_size)
{
    const int*   x  = (const int*)  d_in[0];
    const int*   y  = (const int*)  d_in[1];
    const float* v  = (const float*)d_in[2];
    const int*   s  = (const int*)  d_in[3];
    const float* W1 = (const float*)d_in[4];
    const float* b1 = (const float*)d_in[5];
    const float* W2 = (const float*)d_in[6];
    const float* b2 = (const float*)d_in[7];
    float* out = (float*)d_out;

    const int total = N_ROWS * GPR;
    convert_kernel<<<(total + 255) / 256, 256>>>(W1);
    fwd_kernel<<<BATCH, 128>>>(x, y, v, s, b1, W2, b2, out);
}

// round 9
// speedup vs baseline: 1.7821x; 1.7821x over previous
#include <cuda_runtime.h>
#include <cuda_bf16.h>
#include <cuda_fp16.h>
#include <cuda_fp8.h>
#include <cstdint>

#define N_ROWS      12288        // L1_INPUT_SIZE
#define N_COLS      1030         // L1_OUTPUT_SIZE
#define HID         1024
#define STRIDE8     1040         // padded fp8 row stride bytes (16B multiple)
#define BATCH       8192
#define NFEAT       32
#define L2IN        2048
#define W_SCALE     128.0f       // weight scale into e4m3 normal range
#define INV_SCALE   0.0078125f   // 1/128
#define PSQT_K      0.08f        // 0.5 / (400/64)
#define GPR         260          // groups of 4 cols per row (260*4 = 1040)

// fp8(e4m3) copy of W1*128 (module-static, no runtime alloc)
__device__ __align__(128) unsigned char g_W1f8[(size_t)N_ROWS * STRIDE8];

// ---------------------------------------------------------------------------
// W1 fp32 -> fp8 conversion (R2-proven shape: u32 store per thread)
// ---------------------------------------------------------------------------
__global__ void convert_kernel(const float* __restrict__ W1) {
    int gid = blockIdx.x * blockDim.x + threadIdx.x;
    if (gid >= N_ROWS * GPR) return;
    const int r   = gid / GPR;
    const int g   = gid - r * GPR;
    const int col = g * 4;
    const float* src = W1 + (size_t)r * N_COLS + col;

    float4 w;
    if (col + 4 <= N_COLS) {
        const float2 a = *reinterpret_cast<const float2*>(src);
        const float2 b = *reinterpret_cast<const float2*>(src + 2);
        w = make_float4(a.x, a.y, b.x, b.y);
    } else {
        w.x = (col + 0 < N_COLS) ? src[0] : 0.f;
        w.y = (col + 1 < N_COLS) ? src[1] : 0.f;
        w.z = (col + 2 < N_COLS) ? src[2] : 0.f;
        w.w = (col + 3 < N_COLS) ? src[3] : 0.f;
    }
    const __nv_fp8x2_storage_t lo =
        __nv_cvt_float2_to_fp8x2(make_float2(w.x * W_SCALE, w.y * W_SCALE),
                                 __NV_SATFINITE, __NV_E4M3);
    const __nv_fp8x2_storage_t hi =
        __nv_cvt_float2_to_fp8x2(make_float2(w.z * W_SCALE, w.w * W_SCALE),
                                 __NV_SATFINITE, __NV_E4M3);
    const uint32_t packed = (uint32_t)lo | ((uint32_t)hi << 16);
    *reinterpret_cast<uint32_t*>(g_W1f8 + (size_t)r * STRIDE8 + col) = packed;
}

// ---------------------------------------------------------------------------
// unpack u32 (4×e4m3) -> two half2, fused multiply-accumulate with vh
// ---------------------------------------------------------------------------
__device__ __forceinline__ void fma4_fp8(half2& a0, half2& a1, uint32_t w, half2 vh) {
    uint32_t h0, h1;
    asm("{\n\t"
        ".reg .b16 lo, hi;\n\t"
        "mov.b32 {lo, hi}, %2;\n\t"
        "cvt.rn.f16x2.e4m3x2 %0, lo;\n\t"
        "cvt.rn.f16x2.e4m3x2 %1, hi;\n\t"
        "}" : "=r"(h0), "=r"(h1) : "r"(w));
    a0 = __hfma2(*reinterpret_cast<half2*>(&h0), vh, a0);
    a1 = __hfma2(*reinterpret_cast<half2*>(&h1), vh, a1);
}

// ---------------------------------------------------------------------------
// Main fused kernel: one CTA per batch row, 128 threads, 8 cols/thread/side,
// 4-deep register prefetch (8 LDG.64 in flight/warp), normal cached loads.
// ---------------------------------------------------------------------------
__global__ __launch_bounds__(128)
void fwd_kernel(const int*   __restrict__ x,
                const int*   __restrict__ y,
                const float* __restrict__ v,
                const int*   __restrict__ s,
                const float* __restrict__ b1,
                const float* __restrict__ W2,
                const float* __restrict__ b2,
                float*       __restrict__ out)
{
    __shared__ int2     sxy[NFEAT + 4];    // {offx, offy} bytes; +4 pad for tail prefetch
    __shared__ uint32_t svh[NFEAT];        // v as half2 bits
    __shared__ int      ss_sh;
    __shared__ float    red[4];

    const int b = blockIdx.x;
    const int t = threadIdx.x;

    if (t < NFEAT) {
        const int gi = b * NFEAT + t;
        sxy[t] = make_int2(x[gi] * STRIDE8, y[gi] * STRIDE8);
        const half2 vh = __float2half2_rn(v[gi]);
        svh[t] = *reinterpret_cast<const uint32_t*>(&vh);
    } else if (t < NFEAT + 4) {            // pad so tail prefetches stay in-bounds
        sxy[t] = make_int2(0, 0);
    } else if (t == 64) {
        ss_sh = s[b];
    }
    __syncthreads();

    const unsigned char* basep = g_W1f8 + t * 8;   // this thread's 8 fp8 columns

    // ---- prime the 4-deep prefetch pipeline ----
    uint2 px[4], py[4];
#pragma unroll
    for (int i = 0; i < 4; ++i) {
        const int2 o = sxy[i];
        px[i] = *reinterpret_cast<const uint2*>(basep + o.x);
        py[i] = *reinterpret_cast<const uint2*>(basep + o.y);
    }

    half2 ax[4], ay[4];
#pragma unroll
    for (int j = 0; j < 4; ++j) { ax[j] = __float2half2_rn(0.f); ay[j] = __float2half2_rn(0.f); }

#pragma unroll 4
    for (int a = 0; a < NFEAT; ++a) {
        const int slot = a & 3;
        const uint2 wx = px[slot];
        const uint2 wy = py[slot];
        const int2  on = sxy[a + 4];       // one LDS.64 for both next offsets
        px[slot] = *reinterpret_cast<const uint2*>(basep + on.x);
        py[slot] = *reinterpret_cast<const uint2*>(basep + on.y);

        half2 vh; *reinterpret_cast<uint32_t*>(&vh) = svh[a];
        fma4_fp8(ax[0], ax[1], wx.x, vh);
        fma4_fp8(ax[2], ax[3], wx.y, vh);
        fma4_fp8(ay[0], ay[1], wy.x, vh);
        fma4_fp8(ay[2], ay[3], wy.y, vh);
    }

    // ---- epilogue: relu(acc/128 + b1) dot W2[ss] ----
    const int ss = ss_sh;
    const int col0 = t * 8;
    const float4 b1a = *reinterpret_cast<const float4*>(b1 + col0);
    const float4 b1b = *reinterpret_cast<const float4*>(b1 + col0 + 4);
    const float* w2row = W2 + (size_t)ss * L2IN;
    const float4 wxa = *reinterpret_cast<const float4*>(w2row + col0);
    const float4 wxb = *reinterpret_cast<const float4*>(w2row + col0 + 4);
    const float4 wya = *reinterpret_cast<const float4*>(w2row + HID + col0);
    const float4 wyb = *reinterpret_cast<const float4*>(w2row + HID + col0 + 4);

    const float2 fx0 = __half22float2(ax[0]);
    const float2 fx1 = __half22float2(ax[1]);
    const float2 fx2 = __half22float2(ax[2]);
    const float2 fx3 = __half22float2(ax[3]);
    const float2 fy0 = __half22float2(ay[0]);
    const float2 fy1 = __half22float2(ay[1]);
    const float2 fy2 = __half22float2(ay[2]);
    const float2 fy3 = __half22float2(ay[3]);

    float local = 0.f;
    local = fmaf(fmaxf(fmaf(fx0.x, INV_SCALE, b1a.x), 0.f), wxa.x, local);
    local = fmaf(fmaxf(fmaf(fx0.y, INV_SCALE, b1a.y), 0.f), wxa.y, local);
    local = fmaf(fmaxf(fmaf(fx1.x, INV_SCALE, b1a.z), 0.f), wxa.z, local);
    local = fmaf(fmaxf(fmaf(fx1.y, INV_SCALE, b1a.w), 0.f), wxa.w, local);
    local = fmaf(fmaxf(fmaf(fx2.x, INV_SCALE, b1b.x), 0.f), wxb.x, local);
    local = fmaf(fmaxf(fmaf(fx2.y, INV_SCALE, b1b.y), 0.f), wxb.y, local);
    local = fmaf(fmaxf(fmaf(fx3.x, INV_SCALE, b1b.z), 0.f), wxb.z, local);
    local = fmaf(fmaxf(fmaf(fx3.y, INV_SCALE, b1b.w), 0.f), wxb.w, local);

    local = fmaf(fmaxf(fmaf(fy0.x, INV_SCALE, b1a.x), 0.f), wya.x, local);
    local = fmaf(fmaxf(fmaf(fy0.y, INV_SCALE, b1a.y), 0.f), wya.y, local);
    local = fmaf(fmaxf(fmaf(fy1.x, INV_SCALE, b1a.z), 0.f), wya.z, local);
    local = fmaf(fmaxf(fmaf(fy1.y, INV_SCALE, b1a.w), 0.f), wya.w, local);
    local = fmaf(fmaxf(fmaf(fy2.x, INV_SCALE, b1b.x), 0.f), wyb.x, local);
    local = fmaf(fmaxf(fmaf(fy2.y, INV_SCALE, b1b.y), 0.f), wyb.y, local);
    local = fmaf(fmaxf(fmaf(fy3.x, INV_SCALE, b1b.z), 0.f), wyb.z, local);
    local = fmaf(fmaxf(fmaf(fy3.y, INV_SCALE, b1b.w), 0.f), wyb.w, local);

    // ---- psqt term: (x2 - y2) * PSQT_K ; b1 cancels in the difference ----
    if (t < 64) {
        const int a  = t & 31;
        const int sp = t >> 5;               // 0 = x, 1 = y
        const int2 o = sxy[a];
        const int off = sp ? o.y : o.x;
        const unsigned char wb = g_W1f8[(size_t)off + HID + ss];
        const float wgt = __half2float(
            __nv_cvt_fp8_to_halfraw((__nv_fp8_storage_t)wb, __NV_E4M3));
        half2 vh; *reinterpret_cast<uint32_t*>(&vh) = svh[a];
        const float p = __half2float(__low2half(vh)) * wgt * (PSQT_K * INV_SCALE);
        local += sp ? -p : p;
    }

    // ---- block reduction ----
#pragma unroll
    for (int o = 16; o > 0; o >>= 1)
        local += __shfl_down_sync(0xffffffffu, local, o);
    if ((t & 31) == 0) red[t >> 5] = local;
    __syncthreads();
    if (t == 0) {
        const float c = red[0] + red[1] + red[2] + red[3] + b2[ss];
        out[b] = 1.0f / (1.0f + expf(-c));
    }
}

// ---------------------------------------------------------------------------
extern "C" void kernel_launch(void* const* d_in, const int* in_sizes, int n_in,
                              void* d_out, int out_size)
{
    const int*   x  = (const int*)  d_in[0];
    const int*   y  = (const int*)  d_in[1];
    const float* v  = (const float*)d_in[2];
    const int*   s  = (const int*)  d_in[3];
    const float* W1 = (const float*)d_in[4];
    const float* b1 = (const float*)d_in[5];
    const float* W2 = (const float*)d_in[6];
    const float* b2 = (const float*)d_in[7];
    float* out = (float*)d_out;

    const int total = N_ROWS * GPR;
    convert_kernel<<<(total + 255) / 256, 256>>>(W1);
    fwd_kernel<<<BATCH, 128>>>(x, y, v, s, b1, W2, b2, out);
}